// round 6
// baseline (speedup 1.0000x reference)
#include <cuda_runtime.h>
#include <cstdint>

#define VSZ 50257
#define ESZ 1024
#define HSZ 1024
#define BSZ 64
#define TSZ 512
#define G4  4096   // 4*H
#define NCTA 128

// ---------------- scratch (device globals; no allocation allowed) ----------
static __device__ float    g_xw[(size_t)TSZ * BSZ * G4];  // [t*B+b][4H]
static __device__ uint32_t g_ht[2][BSZ * HSZ];            // h as tf32 bits
static __device__ float    g_h[BSZ * HSZ];                // final h (fp32)
static __device__ float    g_c[BSZ * HSZ];                // final c (fp32)
static __device__ unsigned g_bar;

// ---------------- helpers --------------------------------------------------
__device__ __forceinline__ uint32_t f2tf(float x) {
  uint32_t r;
  asm("cvt.rna.tf32.f32 %0, %1;" : "=r"(r) : "f"(x));
  return r;
}

__device__ __forceinline__ void mma8(float* c, const uint32_t* a, const uint32_t* b) {
  asm volatile(
      "mma.sync.aligned.m16n8k8.row.col.f32.tf32.tf32.f32 "
      "{%0,%1,%2,%3}, {%4,%5,%6,%7}, {%8,%9}, {%0,%1,%2,%3};"
      : "+f"(c[0]), "+f"(c[1]), "+f"(c[2]), "+f"(c[3])
      : "r"(a[0]), "r"(a[1]), "r"(a[2]), "r"(a[3]), "r"(b[0]), "r"(b[1]));
}

__device__ __forceinline__ float sigm(float x) { return 1.0f / (1.0f + expf(-x)); }

__device__ __forceinline__ void cpa16(uint32_t smem_dst, const void* gsrc) {
  asm volatile("cp.async.cg.shared.global [%0], [%1], 16;"
               :: "r"(smem_dst), "l"(gsrc));
}

// ---------------- kernel: zero h0 (tf32) + barrier counter -----------------
__global__ void k_zero() {
  int i = blockIdx.x * blockDim.x + threadIdx.x;
  if (i == 0) g_bar = 0u;
  if (i < BSZ * HSZ) g_ht[0][i] = 0u;
}

// ---------------- kernel: pre-GEMM  XW = gather(emb) @ W_ih^T --------------
__global__ __launch_bounds__(256) void k_pre(const int* __restrict__ reviews,
                                             const float* __restrict__ emb,
                                             const float* __restrict__ W_ih) {
  __shared__ uint32_t sA[128][36];
  __shared__ uint32_t sB[128][36];

  const int tid = threadIdx.x;
  const int m0 = blockIdx.y * 128;
  const int n0 = blockIdx.x * 128;
  const int lane = tid & 31, w = tid >> 5;
  const int wm = w >> 1, wn = w & 1;      // 4 x 2
  const int gid = lane >> 2, tig = lane & 3;

  const float* arow[4];
  const float* brow[4];
#pragma unroll
  for (int i = 0; i < 4; i++) {
    int q = tid + i * 256;
    int r = q >> 3;
    int m = m0 + r;
    int b = m & 63, t = m >> 6;
    int tok = reviews[b * TSZ + t];
    arow[i] = emb + (size_t)tok * ESZ + ((q & 7) << 2);
    brow[i] = W_ih + (size_t)(n0 + r) * ESZ + ((q & 7) << 2);
  }

  float acc[2][8][4] = {};

  for (int k0 = 0; k0 < 1024; k0 += 32) {
#pragma unroll
    for (int i = 0; i < 4; i++) {
      int q = tid + i * 256;
      int r = q >> 3, c4 = (q & 7) << 2;
      float4 va = *(const float4*)(arow[i] + k0);
      sA[r][c4 + 0] = f2tf(va.x); sA[r][c4 + 1] = f2tf(va.y);
      sA[r][c4 + 2] = f2tf(va.z); sA[r][c4 + 3] = f2tf(va.w);
      float4 vb = *(const float4*)(brow[i] + k0);
      sB[r][c4 + 0] = f2tf(vb.x); sB[r][c4 + 1] = f2tf(vb.y);
      sB[r][c4 + 2] = f2tf(vb.z); sB[r][c4 + 3] = f2tf(vb.w);
    }
    __syncthreads();
#pragma unroll
    for (int k8 = 0; k8 < 4; k8++) {
      const int kk = k8 * 8;
      uint32_t af[2][4], bf[8][2];
#pragma unroll
      for (int mt = 0; mt < 2; mt++) {
        int rm = wm * 32 + mt * 16;
        af[mt][0] = sA[rm + gid][kk + tig];
        af[mt][1] = sA[rm + gid + 8][kk + tig];
        af[mt][2] = sA[rm + gid][kk + tig + 4];
        af[mt][3] = sA[rm + gid + 8][kk + tig + 4];
      }
#pragma unroll
      for (int nt = 0; nt < 8; nt++) {
        int rn = wn * 64 + nt * 8;
        bf[nt][0] = sB[rn + gid][kk + tig];
        bf[nt][1] = sB[rn + gid][kk + tig + 4];
      }
#pragma unroll
      for (int mt = 0; mt < 2; mt++)
#pragma unroll
        for (int nt = 0; nt < 8; nt++) mma8(acc[mt][nt], af[mt], bf[nt]);
    }
    __syncthreads();
  }

#pragma unroll
  for (int mt = 0; mt < 2; mt++) {
    int r0 = m0 + wm * 32 + mt * 16 + gid;
#pragma unroll
    for (int nt = 0; nt < 8; nt++) {
      int c = n0 + wn * 64 + nt * 8 + tig * 2;
      float* C0 = g_xw + (size_t)r0 * G4 + c;
      float* C1 = g_xw + (size_t)(r0 + 8) * G4 + c;
      C0[0] = acc[mt][nt][0]; C0[1] = acc[mt][nt][1];
      C1[0] = acc[mt][nt][2]; C1[1] = acc[mt][nt][3];
    }
  }
}

// ---------------- kernel: persistent recurrence v4 -------------------------
// 128 CTAs, 1/SM. CTA bx owns h-cols [bx*8, bx*8+8) -> 32 gate rows in SMEM.
// 8-way warp split-K with PER-WARP private cp.async rings (4 slots x 64x8
// col-slice, stride-12 conflict-free). No __syncthreads in the k loop:
// each warp self-paces on its own cp.async groups. Tree reduce + fused cell.
#define W_WORDS (32 * 1028)
#define SLOT_W  768                 // 64 rows * 12 words
#define NSLOT   4
#define RING_W  (8 * NSLOT * SLOT_W)
#define RSM_BYTES ((W_WORDS + RING_W) * 4)   // 229,888 B

__global__ __launch_bounds__(256) void k_rec(const float* __restrict__ W_hh) {
  extern __shared__ uint32_t sm[];
  uint32_t* sW   = sm;
  uint32_t* ring = sW + W_WORDS;
  float*    red  = (float*)ring;            // reduce buffer (words 0..8192)
  float*    sg   = (float*)(ring + 8192);   // gate tile (after reduce region)

  const int tid = threadIdx.x;
  const int j0 = blockIdx.x * 8;
  const int lane = tid & 31, w = tid >> 5;   // warp w owns k8 slot w
  const int gid = lane >> 2, tig = lane & 3;

  uint32_t* wring = ring + w * NSLOT * SLOT_W;
  const uint32_t wring_b = (uint32_t)__cvta_generic_to_shared(wring);

  // ---- load W_hh slice (32 gate rows x 1024) into SMEM as tf32, once ----
#pragma unroll 4
  for (int i = 0; i < 32; i++) {
    int e = tid + i * 256;
    int r = e >> 8, cc = (e & 255) * 4;
    int wrow = (r >> 3) * HSZ + j0 + (r & 7);
    float4 v = *(const float4*)(W_hh + (size_t)wrow * HSZ + cc);
    uint32_t* d = sW + r * 1028 + cc;
    d[0] = f2tf(v.x); d[1] = f2tf(v.y); d[2] = f2tf(v.z); d[3] = f2tf(v.w);
  }
  __syncthreads();

  float creg[2] = {0.0f, 0.0f};

  for (int t = 0; t < TSZ; t++) {
    const uint32_t* __restrict__ hp = g_ht[t & 1];
    const float* __restrict__ xwb = g_xw + (size_t)t * BSZ * G4;

    // ---- prologue: issue chunks 0..2 into slots 0..2 (per-warp groups) ----
#pragma unroll
    for (int pc = 0; pc < 3; pc++) {
#pragma unroll
      for (int j = 0; j < 4; j++) {
        int row = lane + 32 * (j >> 1), half = j & 1;
        cpa16(wring_b + (pc * SLOT_W + row * 12 + half * 4) * 4,
              hp + row * HSZ + pc * 64 + w * 8 + half * 4);
      }
      asm volatile("cp.async.commit_group;");
    }

    // prefetch this step's xw gate biases (independent DRAM loads)
    float xwp[8];
#pragma unroll
    for (int s = 0; s < 2; s++) {
      int idx = tid + s * 256;
      int b = idx >> 3, jj = idx & 7, j = j0 + jj;
      const float* xw = xwb + (size_t)b * G4;
      xwp[s * 4 + 0] = __ldcs(xw + j);
      xwp[s * 4 + 1] = __ldcs(xw + HSZ + j);
      xwp[s * 4 + 2] = __ldcs(xw + 2 * HSZ + j);
      xwp[s * 4 + 3] = __ldcs(xw + 3 * HSZ + j);
    }

    float4 acc4[4][4];
#pragma unroll
    for (int mt = 0; mt < 4; mt++)
#pragma unroll
      for (int nt = 0; nt < 4; nt++) acc4[mt][nt] = make_float4(0.f, 0.f, 0.f, 0.f);

    // ---- k loop: NO cross-warp sync; each warp self-paced ----
    for (int kc = 0; kc < 16; kc++) {
      if (kc <= 13)      asm volatile("cp.async.wait_group 2;");
      else if (kc == 14) asm volatile("cp.async.wait_group 1;");
      else               asm volatile("cp.async.wait_group 0;");

      if (kc < 13) {
        const int nc = kc + 3;
        const int sl = nc & 3;
#pragma unroll
        for (int j = 0; j < 4; j++) {
          int row = lane + 32 * (j >> 1), half = j & 1;
          cpa16(wring_b + (sl * SLOT_W + row * 12 + half * 4) * 4,
                hp + row * HSZ + nc * 64 + w * 8 + half * 4);
        }
        asm volatile("cp.async.commit_group;");
      }

      const uint32_t* su = wring + (kc & 3) * SLOT_W;
      uint32_t af[4][4], bf[4][2];
      const int kt = kc * 64 + w * 8;
#pragma unroll
      for (int mt = 0; mt < 4; mt++) {
        int ra = (mt * 16 + gid) * 12 + tig;
        af[mt][0] = su[ra];
        af[mt][1] = su[ra + 8 * 12];
        af[mt][2] = su[ra + 4];
        af[mt][3] = su[ra + 8 * 12 + 4];
      }
#pragma unroll
      for (int nt = 0; nt < 4; nt++) {
        int rb = (nt * 8 + gid) * 1028 + kt + tig;
        bf[nt][0] = sW[rb];
        bf[nt][1] = sW[rb + 4];
      }
#pragma unroll
      for (int mt = 0; mt < 4; mt++)
#pragma unroll
        for (int nt = 0; nt < 4; nt++)
          mma8((float*)&acc4[mt][nt], af[mt], bf[nt]);
    }

    __syncthreads();   // all warps done reading their rings -> safe to reuse

    // ---- tree-reduce the 8 warps' partial tiles into warp 0 ----
#pragma unroll
    for (int half = 4; half >= 1; half >>= 1) {
      if (w >= half && w < 2 * half) {
#pragma unroll
        for (int mt = 0; mt < 4; mt++)
#pragma unroll
          for (int nt = 0; nt < 4; nt++)
            *(float4*)(red + (w - half) * 2048 + ((mt * 4 + nt) * 32 + lane) * 4)
                = acc4[mt][nt];
      }
      __syncthreads();
      if (w < half) {
#pragma unroll
        for (int mt = 0; mt < 4; mt++)
#pragma unroll
          for (int nt = 0; nt < 4; nt++) {
            float4 v = *(const float4*)(red + w * 2048 + ((mt * 4 + nt) * 32 + lane) * 4);
            acc4[mt][nt].x += v.x; acc4[mt][nt].y += v.y;
            acc4[mt][nt].z += v.z; acc4[mt][nt].w += v.w;
          }
      }
      __syncthreads();
    }

    // warp 0 holds the full 64x32 gate tile -> sg
    if (w == 0) {
#pragma unroll
      for (int mt = 0; mt < 4; mt++) {
        int r0 = mt * 16 + gid;
#pragma unroll
        for (int nt = 0; nt < 4; nt++) {
          int c = nt * 8 + tig * 2;
          sg[r0 * 33 + c]           = acc4[mt][nt].x;
          sg[r0 * 33 + c + 1]       = acc4[mt][nt].y;
          sg[(r0 + 8) * 33 + c]     = acc4[mt][nt].z;
          sg[(r0 + 8) * 33 + c + 1] = acc4[mt][nt].w;
        }
      }
    }
    __syncthreads();

    // fused LSTM pointwise; c in registers; h written as tf32
    uint32_t* __restrict__ hn = g_ht[(t + 1) & 1];
#pragma unroll
    for (int s = 0; s < 2; s++) {
      int idx = tid + s * 256;
      int b = idx >> 3, jj = idx & 7, j = j0 + jj;
      float iv = sg[b * 33 + jj]      + xwp[s * 4 + 0];
      float fv = sg[b * 33 + 8 + jj]  + xwp[s * 4 + 1];
      float gv = sg[b * 33 + 16 + jj] + xwp[s * 4 + 2];
      float ov = sg[b * 33 + 24 + jj] + xwp[s * 4 + 3];
      float c2 = sigm(fv) * creg[s] + sigm(iv) * tanhf(gv);
      float h2 = sigm(ov) * tanhf(c2);
      creg[s] = c2;
      __stcg(hn + b * HSZ + j, f2tf(h2));
      if (t == TSZ - 1) {
        g_h[b * HSZ + j] = h2;
        g_c[b * HSZ + j] = c2;
      }
    }

    // ---- grid barrier: monotonic counter + bounded-spin backoff ----
    __syncthreads();
    if (tid == 0) {
      __threadfence();
      unsigned arr = atomicAdd(&g_bar, 1u) + 1u;
      unsigned target = (unsigned)(t + 1) * NCTA;
      if (arr != target) {
        int spin = 0;
        while (*((volatile unsigned*)&g_bar) < target) {
          if (++spin > 64) { __nanosleep(32); spin = 0; }
        }
      }
      __threadfence();
    }
    __syncthreads();
  }
}

// ---------------- kernel: classifier  logits = h @ W_cls^T + b -------------
__global__ __launch_bounds__(256) void k_cls(const float* __restrict__ W_cls,
                                             const float* __restrict__ b_cls,
                                             float* __restrict__ out) {
  __shared__ uint32_t sA[64][36];
  __shared__ uint32_t sB[128][36];
  const int tid = threadIdx.x;
  const int n0 = blockIdx.x * 128;
  const uint32_t* __restrict__ A = g_ht[0];   // final h, already tf32

  const int lane = tid & 31, w = tid >> 5;
  const int wm = w >> 2, wn = w & 3;
  const int gid = lane >> 2, tig = lane & 3;

  const uint32_t* arow[2];
  const float* brow[4];
#pragma unroll
  for (int i = 0; i < 2; i++) {
    int q = tid + i * 256;
    int r = q >> 3;
    arow[i] = A + (size_t)r * HSZ + ((q & 7) << 2);
  }
#pragma unroll
  for (int i = 0; i < 4; i++) {
    int q = tid + i * 256;
    int r = q >> 3;
    int n = n0 + r; if (n > VSZ - 1) n = VSZ - 1;
    brow[i] = W_cls + (size_t)n * HSZ + ((q & 7) << 2);
  }

  float acc[2][4][4] = {};

  for (int k0 = 0; k0 < 1024; k0 += 32) {
#pragma unroll
    for (int i = 0; i < 2; i++) {
      int q = tid + i * 256;
      int r = q >> 3, c4 = (q & 7) << 2;
      uint4 va = *(const uint4*)(arow[i] + k0);
      sA[r][c4 + 0] = va.x; sA[r][c4 + 1] = va.y;
      sA[r][c4 + 2] = va.z; sA[r][c4 + 3] = va.w;
    }
#pragma unroll
    for (int i = 0; i < 4; i++) {
      int q = tid + i * 256;
      int r = q >> 3, c4 = (q & 7) << 2;
      float4 vb = *(const float4*)(brow[i] + k0);
      sB[r][c4 + 0] = f2tf(vb.x); sB[r][c4 + 1] = f2tf(vb.y);
      sB[r][c4 + 2] = f2tf(vb.z); sB[r][c4 + 3] = f2tf(vb.w);
    }
    __syncthreads();
#pragma unroll
    for (int k8 = 0; k8 < 4; k8++) {
      const int kk = k8 * 8;
      uint32_t af[2][4], bf[4][2];
#pragma unroll
      for (int mt = 0; mt < 2; mt++) {
        int rm = wm * 32 + mt * 16;
        af[mt][0] = sA[rm + gid][kk + tig];
        af[mt][1] = sA[rm + gid + 8][kk + tig];
        af[mt][2] = sA[rm + gid][kk + tig + 4];
        af[mt][3] = sA[rm + gid + 8][kk + tig + 4];
      }
#pragma unroll
      for (int nt = 0; nt < 4; nt++) {
        int rn = wn * 32 + nt * 8;
        bf[nt][0] = sB[rn + gid][kk + tig];
        bf[nt][1] = sB[rn + gid][kk + tig + 4];
      }
#pragma unroll
      for (int mt = 0; mt < 2; mt++)
#pragma unroll
        for (int nt = 0; nt < 4; nt++) mma8(acc[mt][nt], af[mt], bf[nt]);
    }
    __syncthreads();
  }

#pragma unroll
  for (int mt = 0; mt < 2; mt++) {
    int r0 = wm * 32 + mt * 16 + gid;
#pragma unroll
    for (int nt = 0; nt < 4; nt++) {
      int c = n0 + wn * 32 + nt * 8 + tig * 2;
      if (c < VSZ)     out[(size_t)r0 * VSZ + c]           = acc[mt][nt][0] + b_cls[c];
      if (c + 1 < VSZ) out[(size_t)r0 * VSZ + c + 1]       = acc[mt][nt][1] + b_cls[c + 1];
      if (c < VSZ)     out[(size_t)(r0 + 8) * VSZ + c]     = acc[mt][nt][2] + b_cls[c];
      if (c + 1 < VSZ) out[(size_t)(r0 + 8) * VSZ + c + 1] = acc[mt][nt][3] + b_cls[c + 1];
    }
  }
}

// ---------------- kernel: copy final h, c into output ----------------------
__global__ void k_tail(float* __restrict__ out) {
  int i = blockIdx.x * blockDim.x + threadIdx.x;
  const size_t OH = (size_t)BSZ * VSZ;
  if (i < BSZ * HSZ) {
    out[OH + i]             = g_h[i];
    out[OH + BSZ * HSZ + i] = g_c[i];
  }
}

// ---------------- launch ---------------------------------------------------
extern "C" void kernel_launch(void* const* d_in, const int* in_sizes, int n_in,
                              void* d_out, int out_size) {
  const int*   reviews = (const int*)d_in[0];
  const float* emb     = (const float*)d_in[1];
  const float* W_ih    = (const float*)d_in[2];
  const float* W_hh    = (const float*)d_in[3];
  const float* W_cls   = (const float*)d_in[4];
  const float* b_cls   = (const float*)d_in[5];
  float* out = (float*)d_out;

  static bool attr_set = false;
  if (!attr_set) {
    cudaFuncSetAttribute(k_rec, cudaFuncAttributeMaxDynamicSharedMemorySize,
                         RSM_BYTES);
    attr_set = true;
  }

  k_zero<<<(BSZ * HSZ + 255) / 256, 256>>>();
  k_pre<<<dim3(G4 / 128, (TSZ * BSZ) / 128), 256>>>(reviews, emb, W_ih);
  k_rec<<<NCTA, 256, RSM_BYTES>>>(W_hh);
  k_cls<<<(VSZ + 127) / 128, 256>>>(W_cls, b_cls, out);
  k_tail<<<(BSZ * HSZ + 255) / 256, 256>>>(out);
}

// round 7
// speedup vs baseline: 1.3975x; 1.3975x over previous
#include <cuda_runtime.h>
#include <cstdint>

#define VSZ 50257
#define ESZ 1024
#define HSZ 1024
#define BSZ 64
#define TSZ 512
#define G4  4096   // 4*H
#define NCTA 128

#define CHUNK_W 4352          // one h chunk: 64 rows * 68 cols (tf32 words)
#define CHUNK_BYTES 17408
#define NCHUNK 16

// ---------------- scratch (device globals; no allocation allowed) ----------
static __device__ float    g_xw[(size_t)TSZ * BSZ * G4];   // [t*B+b][4H]
static __device__ __align__(16) uint32_t g_ht[2][NCHUNK * CHUNK_W]; // padded tf32 h
static __device__ uint32_t g_htd[BSZ * HSZ];               // dense tf32 final h
static __device__ float    g_h[BSZ * HSZ];                 // final h (fp32)
static __device__ float    g_c[BSZ * HSZ];                 // final c (fp32)
static __device__ unsigned g_bar;

// ---------------- helpers --------------------------------------------------
__device__ __forceinline__ uint32_t f2tf(float x) {
  uint32_t r;
  asm("cvt.rna.tf32.f32 %0, %1;" : "=r"(r) : "f"(x));
  return r;
}

__device__ __forceinline__ void mma8(float* c, const uint32_t* a, const uint32_t* b) {
  asm volatile(
      "mma.sync.aligned.m16n8k8.row.col.f32.tf32.tf32.f32 "
      "{%0,%1,%2,%3}, {%4,%5,%6,%7}, {%8,%9}, {%0,%1,%2,%3};"
      : "+f"(c[0]), "+f"(c[1]), "+f"(c[2]), "+f"(c[3])
      : "r"(a[0]), "r"(a[1]), "r"(a[2]), "r"(a[3]), "r"(b[0]), "r"(b[1]));
}

__device__ __forceinline__ float sigm(float x) { return 1.0f / (1.0f + expf(-x)); }

__device__ __forceinline__ void mbar_init(uint32_t a, uint32_t cnt) {
  asm volatile("mbarrier.init.shared.b64 [%0], %1;" :: "r"(a), "r"(cnt) : "memory");
}
__device__ __forceinline__ void mbar_expect_tx(uint32_t a, uint32_t tx) {
  asm volatile("mbarrier.arrive.expect_tx.shared.b64 _, [%0], %1;"
               :: "r"(a), "r"(tx) : "memory");
}
__device__ __forceinline__ void mbar_arrive(uint32_t a) {
  asm volatile("mbarrier.arrive.shared.b64 _, [%0];" :: "r"(a) : "memory");
}
__device__ __forceinline__ void mbar_wait(uint32_t a, uint32_t parity) {
  asm volatile(
      "{\n\t.reg .pred P;\n"
      "W%=:\n\t"
      "mbarrier.try_wait.parity.acquire.cta.shared::cta.b64 P, [%0], %1, 0x989680;\n\t"
      "@P bra D%=;\n\t"
      "bra W%=;\n"
      "D%=:\n\t}"
      :: "r"(a), "r"(parity) : "memory");
}
__device__ __forceinline__ void bulk_g2s(uint32_t dst, const void* src,
                                         uint32_t bytes, uint32_t mbar) {
  asm volatile(
      "cp.async.bulk.shared::cluster.global.mbarrier::complete_tx::bytes "
      "[%0], [%1], %2, [%3];"
      :: "r"(dst), "l"(src), "r"(bytes), "r"(mbar) : "memory");
}

// ---------------- kernel: zero h0 (padded tf32) + barrier counter ----------
__global__ void k_zero() {
  int i = blockIdx.x * blockDim.x + threadIdx.x;
  if (i == 0) g_bar = 0u;
  if (i < NCHUNK * CHUNK_W) g_ht[0][i] = 0u;
}

// ---------------- kernel: pre-GEMM  XW = gather(emb) @ W_ih^T --------------
__global__ __launch_bounds__(256) void k_pre(const int* __restrict__ reviews,
                                             const float* __restrict__ emb,
                                             const float* __restrict__ W_ih) {
  __shared__ uint32_t sA[128][36];
  __shared__ uint32_t sB[128][36];

  const int tid = threadIdx.x;
  const int m0 = blockIdx.y * 128;
  const int n0 = blockIdx.x * 128;
  const int lane = tid & 31, w = tid >> 5;
  const int wm = w >> 1, wn = w & 1;      // 4 x 2
  const int gid = lane >> 2, tig = lane & 3;

  const float* arow[4];
  const float* brow[4];
#pragma unroll
  for (int i = 0; i < 4; i++) {
    int q = tid + i * 256;
    int r = q >> 3;
    int m = m0 + r;
    int b = m & 63, t = m >> 6;
    int tok = reviews[b * TSZ + t];
    arow[i] = emb + (size_t)tok * ESZ + ((q & 7) << 2);
    brow[i] = W_ih + (size_t)(n0 + r) * ESZ + ((q & 7) << 2);
  }

  float acc[2][8][4] = {};

  for (int k0 = 0; k0 < 1024; k0 += 32) {
#pragma unroll
    for (int i = 0; i < 4; i++) {
      int q = tid + i * 256;
      int r = q >> 3, c4 = (q & 7) << 2;
      float4 va = *(const float4*)(arow[i] + k0);
      sA[r][c4 + 0] = f2tf(va.x); sA[r][c4 + 1] = f2tf(va.y);
      sA[r][c4 + 2] = f2tf(va.z); sA[r][c4 + 3] = f2tf(va.w);
      float4 vb = *(const float4*)(brow[i] + k0);
      sB[r][c4 + 0] = f2tf(vb.x); sB[r][c4 + 1] = f2tf(vb.y);
      sB[r][c4 + 2] = f2tf(vb.z); sB[r][c4 + 3] = f2tf(vb.w);
    }
    __syncthreads();
#pragma unroll
    for (int k8 = 0; k8 < 4; k8++) {
      const int kk = k8 * 8;
      uint32_t af[2][4], bf[8][2];
#pragma unroll
      for (int mt = 0; mt < 2; mt++) {
        int rm = wm * 32 + mt * 16;
        af[mt][0] = sA[rm + gid][kk + tig];
        af[mt][1] = sA[rm + gid + 8][kk + tig];
        af[mt][2] = sA[rm + gid][kk + tig + 4];
        af[mt][3] = sA[rm + gid + 8][kk + tig + 4];
      }
#pragma unroll
      for (int nt = 0; nt < 8; nt++) {
        int rn = wn * 64 + nt * 8;
        bf[nt][0] = sB[rn + gid][kk + tig];
        bf[nt][1] = sB[rn + gid][kk + tig + 4];
      }
#pragma unroll
      for (int mt = 0; mt < 2; mt++)
#pragma unroll
        for (int nt = 0; nt < 8; nt++) mma8(acc[mt][nt], af[mt], bf[nt]);
    }
    __syncthreads();
  }

#pragma unroll
  for (int mt = 0; mt < 2; mt++) {
    int r0 = m0 + wm * 32 + mt * 16 + gid;
#pragma unroll
    for (int nt = 0; nt < 8; nt++) {
      int c = n0 + wn * 64 + nt * 8 + tig * 2;
      float* C0 = g_xw + (size_t)r0 * G4 + c;
      float* C1 = g_xw + (size_t)(r0 + 8) * G4 + c;
      C0[0] = acc[mt][nt][0]; C0[1] = acc[mt][nt][1];
      C1[0] = acc[mt][nt][2]; C1[1] = acc[mt][nt][3];
    }
  }
}

// ---------------- kernel: persistent recurrence v5 -------------------------
// 128 CTAs, 1/SM. CTA bx owns h-cols [bx*8, bx*8+8) -> 32 gate rows in SMEM.
// h lives in global PRE-PADDED to the smem tile shape [16][64][68] tf32, so
// each 17KB chunk is ONE cp.async.bulk into a 4-slot mbarrier ring.
// 8-way warp split-K + tree reduce; c in registers; grid barrier.
#define MBAR_W  32                      // 8 mbarriers (full[4], empty[4])
#define W_WORDS (32 * 1028)
#define RING_W  (4 * CHUNK_W)
#define SG_W    (64 * 33)
#define RSM_BYTES ((MBAR_W + W_WORDS + RING_W + SG_W) * 4)   // 209,792 B

__global__ __launch_bounds__(256) void k_rec(const float* __restrict__ W_hh) {
  extern __shared__ uint32_t sm[];
  uint32_t* sW   = sm + MBAR_W;
  uint32_t* ring = sW + W_WORDS;
  float*    sg   = (float*)(ring + RING_W);
  float*    red  = (float*)ring;            // reduce buffer (aliases slots 0-1)

  const int tid = threadIdx.x;
  const int j0 = blockIdx.x * 8;
  const int lane = tid & 31, w = tid >> 5;   // warp w owns k8 slot w
  const int gid = lane >> 2, tig = lane & 3;

  const uint32_t mb_b   = (uint32_t)__cvta_generic_to_shared(sm);
  const uint32_t ring_b = (uint32_t)__cvta_generic_to_shared(ring);

  if (tid == 0) {
#pragma unroll
    for (int s = 0; s < 4; s++) {
      mbar_init(mb_b + s * 8, 1);        // full[s]: tx-based
      mbar_init(mb_b + 32 + s * 8, 8);   // empty[s]: 8 warp arrivals
    }
  }

  // ---- load W_hh slice (32 gate rows x 1024) into SMEM as tf32, once ----
#pragma unroll 4
  for (int i = 0; i < 32; i++) {
    int e = tid + i * 256;
    int r = e >> 8, cc = (e & 255) * 4;
    int wrow = (r >> 3) * HSZ + j0 + (r & 7);
    float4 v = *(const float4*)(W_hh + (size_t)wrow * HSZ + cc);
    uint32_t* d = sW + r * 1028 + cc;
    d[0] = f2tf(v.x); d[1] = f2tf(v.y); d[2] = f2tf(v.z); d[3] = f2tf(v.w);
  }
  __syncthreads();

  float creg[2] = {0.0f, 0.0f};

  for (int t = 0; t < TSZ; t++) {
    const uint32_t* __restrict__ hp = g_ht[t & 1];
    const float* __restrict__ xwb = g_xw + (size_t)t * BSZ * G4;

    // ---- producer prologue: issue chunks 0..2 ----
    if (tid == 0) {
      unsigned U0 = (unsigned)t * 4u;     // use index for chunks 0..3
#pragma unroll
      for (int pc = 0; pc < 3; pc++) {
        if (U0 > 0) mbar_wait(mb_b + 32 + pc * 8, (U0 - 1) & 1);
        mbar_expect_tx(mb_b + pc * 8, CHUNK_BYTES);
        bulk_g2s(ring_b + pc * CHUNK_BYTES, hp + pc * CHUNK_W,
                 CHUNK_BYTES, mb_b + pc * 8);
      }
    }

    // prefetch this step's xw gate biases (independent DRAM loads)
    float xwp[8];
#pragma unroll
    for (int s = 0; s < 2; s++) {
      int idx = tid + s * 256;
      int b = idx >> 3, jj = idx & 7, j = j0 + jj;
      const float* xw = xwb + (size_t)b * G4;
      xwp[s * 4 + 0] = __ldcs(xw + j);
      xwp[s * 4 + 1] = __ldcs(xw + HSZ + j);
      xwp[s * 4 + 2] = __ldcs(xw + 2 * HSZ + j);
      xwp[s * 4 + 3] = __ldcs(xw + 3 * HSZ + j);
    }

    float4 acc4[4][4];
#pragma unroll
    for (int mt = 0; mt < 4; mt++)
#pragma unroll
      for (int nt = 0; nt < 4; nt++) acc4[mt][nt] = make_float4(0.f, 0.f, 0.f, 0.f);

    // ---- k loop: mbarrier-paced, no __syncthreads ----
    for (int kc = 0; kc < 16; kc++) {
      if (tid == 0 && kc < 13) {
        const int nc = kc + 3, s = nc & 3;
        unsigned U = (unsigned)t * 4u + (unsigned)(nc >> 2);
        mbar_wait(mb_b + 32 + s * 8, (U - 1) & 1);   // U >= 3 here when t==0
        mbar_expect_tx(mb_b + s * 8, CHUNK_BYTES);
        bulk_g2s(ring_b + s * CHUNK_BYTES, hp + nc * CHUNK_W,
                 CHUNK_BYTES, mb_b + s * 8);
      }

      // consumer: wait chunk kc
      {
        unsigned U = (unsigned)t * 4u + (unsigned)(kc >> 2);
        mbar_wait(mb_b + (kc & 3) * 8, U & 1);
      }

      const uint32_t* sAc = ring + (kc & 3) * CHUNK_W;
      uint32_t af[4][4], bf[4][2];
      const int kk = w * 8;
      const int kt = kc * 64 + kk;
#pragma unroll
      for (int mt = 0; mt < 4; mt++) {
        int ra = (mt * 16 + gid) * 68 + kk + tig;
        af[mt][0] = sAc[ra];
        af[mt][1] = sAc[ra + 8 * 68];
        af[mt][2] = sAc[ra + 4];
        af[mt][3] = sAc[ra + 8 * 68 + 4];
      }
#pragma unroll
      for (int nt = 0; nt < 4; nt++) {
        int rb = (nt * 8 + gid) * 1028 + kt + tig;
        bf[nt][0] = sW[rb];
        bf[nt][1] = sW[rb + 4];
      }
#pragma unroll
      for (int mt = 0; mt < 4; mt++)
#pragma unroll
        for (int nt = 0; nt < 4; nt++)
          mma8((float*)&acc4[mt][nt], af[mt], bf[nt]);

      if (lane == 0) mbar_arrive(mb_b + 32 + (kc & 3) * 8);
    }

    __syncthreads();   // all warps done reading ring -> safe to reuse as red

    // ---- tree-reduce the 8 warps' partial tiles into warp 0 ----
#pragma unroll
    for (int half = 4; half >= 1; half >>= 1) {
      if (w >= half && w < 2 * half) {
#pragma unroll
        for (int mt = 0; mt < 4; mt++)
#pragma unroll
          for (int nt = 0; nt < 4; nt++)
            *(float4*)(red + (w - half) * 2048 + ((mt * 4 + nt) * 32 + lane) * 4)
                = acc4[mt][nt];
      }
      __syncthreads();
      if (w < half) {
#pragma unroll
        for (int mt = 0; mt < 4; mt++)
#pragma unroll
          for (int nt = 0; nt < 4; nt++) {
            float4 v = *(const float4*)(red + w * 2048 + ((mt * 4 + nt) * 32 + lane) * 4);
            acc4[mt][nt].x += v.x; acc4[mt][nt].y += v.y;
            acc4[mt][nt].z += v.z; acc4[mt][nt].w += v.w;
          }
      }
      __syncthreads();
    }

    // warp 0 holds the full 64x32 gate tile -> sg
    if (w == 0) {
#pragma unroll
      for (int mt = 0; mt < 4; mt++) {
        int r0 = mt * 16 + gid;
#pragma unroll
        for (int nt = 0; nt < 4; nt++) {
          int c = nt * 8 + tig * 2;
          sg[r0 * 33 + c]           = acc4[mt][nt].x;
          sg[r0 * 33 + c + 1]       = acc4[mt][nt].y;
          sg[(r0 + 8) * 33 + c]     = acc4[mt][nt].z;
          sg[(r0 + 8) * 33 + c + 1] = acc4[mt][nt].w;
        }
      }
    }
    __syncthreads();

    // fused LSTM pointwise; c in registers; h written as padded tf32
    uint32_t* __restrict__ hn = g_ht[(t + 1) & 1];
#pragma unroll
    for (int s = 0; s < 2; s++) {
      int idx = tid + s * 256;
      int b = idx >> 3, jj = idx & 7, j = j0 + jj;
      float iv = sg[b * 33 + jj]      + xwp[s * 4 + 0];
      float fv = sg[b * 33 + 8 + jj]  + xwp[s * 4 + 1];
      float gv = sg[b * 33 + 16 + jj] + xwp[s * 4 + 2];
      float ov = sg[b * 33 + 24 + jj] + xwp[s * 4 + 3];
      float c2 = sigm(fv) * creg[s] + sigm(iv) * tanhf(gv);
      float h2 = sigm(ov) * tanhf(c2);
      creg[s] = c2;
      uint32_t htv = f2tf(h2);
      __stcg(hn + (j >> 6) * CHUNK_W + b * 68 + (j & 63), htv);
      if (t == TSZ - 1) {
        g_htd[b * HSZ + j] = htv;
        g_h[b * HSZ + j] = h2;
        g_c[b * HSZ + j] = c2;
      }
    }

    // ---- grid barrier: monotonic counter + bounded-spin backoff ----
    __syncthreads();
    if (tid == 0) {
      __threadfence();
      unsigned arr = atomicAdd(&g_bar, 1u) + 1u;
      unsigned target = (unsigned)(t + 1) * NCTA;
      if (arr != target) {
        int spin = 0;
        while (*((volatile unsigned*)&g_bar) < target) {
          if (++spin > 64) { __nanosleep(32); spin = 0; }
        }
      }
      __threadfence();
    }
    __syncthreads();
  }
}

// ---------------- kernel: classifier  logits = h @ W_cls^T + b -------------
__global__ __launch_bounds__(256) void k_cls(const float* __restrict__ W_cls,
                                             const float* __restrict__ b_cls,
                                             float* __restrict__ out) {
  __shared__ uint32_t sA[64][36];
  __shared__ uint32_t sB[128][36];
  const int tid = threadIdx.x;
  const int n0 = blockIdx.x * 128;
  const uint32_t* __restrict__ A = g_htd;   // final h, dense tf32

  const int lane = tid & 31, w = tid >> 5;
  const int wm = w >> 2, wn = w & 3;
  const int gid = lane >> 2, tig = lane & 3;

  const uint32_t* arow[2];
  const float* brow[4];
#pragma unroll
  for (int i = 0; i < 2; i++) {
    int q = tid + i * 256;
    int r = q >> 3;
    arow[i] = A + (size_t)r * HSZ + ((q & 7) << 2);
  }
#pragma unroll
  for (int i = 0; i < 4; i++) {
    int q = tid + i * 256;
    int r = q >> 3;
    int n = n0 + r; if (n > VSZ - 1) n = VSZ - 1;
    brow[i] = W_cls + (size_t)n * HSZ + ((q & 7) << 2);
  }

  float acc[2][4][4] = {};

  for (int k0 = 0; k0 < 1024; k0 += 32) {
#pragma unroll
    for (int i = 0; i < 2; i++) {
      int q = tid + i * 256;
      int r = q >> 3, c4 = (q & 7) << 2;
      uint4 va = *(const uint4*)(arow[i] + k0);
      sA[r][c4 + 0] = va.x; sA[r][c4 + 1] = va.y;
      sA[r][c4 + 2] = va.z; sA[r][c4 + 3] = va.w;
    }
#pragma unroll
    for (int i = 0; i < 4; i++) {
      int q = tid + i * 256;
      int r = q >> 3, c4 = (q & 7) << 2;
      float4 vb = *(const float4*)(brow[i] + k0);
      sB[r][c4 + 0] = f2tf(vb.x); sB[r][c4 + 1] = f2tf(vb.y);
      sB[r][c4 + 2] = f2tf(vb.z); sB[r][c4 + 3] = f2tf(vb.w);
    }
    __syncthreads();
#pragma unroll
    for (int k8 = 0; k8 < 4; k8++) {
      const int kk = k8 * 8;
      uint32_t af[2][4], bf[4][2];
#pragma unroll
      for (int mt = 0; mt < 2; mt++) {
        int rm = wm * 32 + mt * 16;
        af[mt][0] = sA[rm + gid][kk + tig];
        af[mt][1] = sA[rm + gid + 8][kk + tig];
        af[mt][2] = sA[rm + gid][kk + tig + 4];
        af[mt][3] = sA[rm + gid + 8][kk + tig + 4];
      }
#pragma unroll
      for (int nt = 0; nt < 4; nt++) {
        int rn = wn * 32 + nt * 8;
        bf[nt][0] = sB[rn + gid][kk + tig];
        bf[nt][1] = sB[rn + gid][kk + tig + 4];
      }
#pragma unroll
      for (int mt = 0; mt < 2; mt++)
#pragma unroll
        for (int nt = 0; nt < 4; nt++) mma8(acc[mt][nt], af[mt], bf[nt]);
    }
    __syncthreads();
  }

#pragma unroll
  for (int mt = 0; mt < 2; mt++) {
    int r0 = wm * 32 + mt * 16 + gid;
#pragma unroll
    for (int nt = 0; nt < 4; nt++) {
      int c = n0 + wn * 32 + nt * 8 + tig * 2;
      if (c < VSZ)     out[(size_t)r0 * VSZ + c]           = acc[mt][nt][0] + b_cls[c];
      if (c + 1 < VSZ) out[(size_t)r0 * VSZ + c + 1]       = acc[mt][nt][1] + b_cls[c + 1];
      if (c < VSZ)     out[(size_t)(r0 + 8) * VSZ + c]     = acc[mt][nt][2] + b_cls[c];
      if (c + 1 < VSZ) out[(size_t)(r0 + 8) * VSZ + c + 1] = acc[mt][nt][3] + b_cls[c + 1];
    }
  }
}

// ---------------- kernel: copy final h, c into output ----------------------
__global__ void k_tail(float* __restrict__ out) {
  int i = blockIdx.x * blockDim.x + threadIdx.x;
  const size_t OH = (size_t)BSZ * VSZ;
  if (i < BSZ * HSZ) {
    out[OH + i]             = g_h[i];
    out[OH + BSZ * HSZ + i] = g_c[i];
  }
}

// ---------------- launch ---------------------------------------------------
extern "C" void kernel_launch(void* const* d_in, const int* in_sizes, int n_in,
                              void* d_out, int out_size) {
  const int*   reviews = (const int*)d_in[0];
  const float* emb     = (const float*)d_in[1];
  const float* W_ih    = (const float*)d_in[2];
  const float* W_hh    = (const float*)d_in[3];
  const float* W_cls   = (const float*)d_in[4];
  const float* b_cls   = (const float*)d_in[5];
  float* out = (float*)d_out;

  static bool attr_set = false;
  if (!attr_set) {
    cudaFuncSetAttribute(k_rec, cudaFuncAttributeMaxDynamicSharedMemorySize,
                         RSM_BYTES);
    attr_set = true;
  }

  k_zero<<<(NCHUNK * CHUNK_W + 255) / 256, 256>>>();
  k_pre<<<dim3(G4 / 128, (TSZ * BSZ) / 128), 256>>>(reviews, emb, W_ih);
  k_rec<<<NCTA, 256, RSM_BYTES>>>(W_hh);
  k_cls<<<(VSZ + 127) / 128, 256>>>(W_cls, b_cls, out);
  k_tail<<<(BSZ * HSZ + 255) / 256, 256>>>(out);
}